// round 1
// baseline (speedup 1.0000x reference)
#include <cuda_runtime.h>
#include <cuda_bf16.h>

// Problem constants (fixed shapes: src/dst [8, 256, 48, 48])
#define BB 8
#define CC 256
#define SS 2304   // 48*48

// GEMM tiling
#define BM 128
#define BN 128
#define BK 16

// Scratch for inverse channel norms (no cudaMalloc allowed)
__device__ float g_inv_src[BB * SS];
__device__ float g_inv_dst[BB * SS];

// ---------------------------------------------------------------------------
// Kernel 1: inv_norm[b][s] = rsqrt( sum_c x[b][c][s]^2 )  for src and dst
// ---------------------------------------------------------------------------
__global__ void inv_norm_kernel(const float* __restrict__ src,
                                const float* __restrict__ dst) {
    int idx = blockIdx.x * blockDim.x + threadIdx.x;
    const int total = BB * SS;
    const float* base;
    float* outp;
    int i = idx;
    if (idx < total) {
        base = src; outp = g_inv_src;
    } else {
        base = dst; outp = g_inv_dst; i -= total;
    }
    int b = i / SS;
    int s = i - b * SS;
    const float* p = base + (size_t)b * CC * SS + s;
    float acc = 0.0f;
#pragma unroll 8
    for (int c = 0; c < CC; ++c) {
        float v = p[(size_t)c * SS];
        acc = fmaf(v, v, acc);
    }
    outp[i] = rsqrtf(acc);
}

// ---------------------------------------------------------------------------
// Packed f32x2 helpers (Blackwell sm_103a: fma.rn.f32x2)
// ---------------------------------------------------------------------------
__device__ __forceinline__ unsigned long long fma2(unsigned long long a,
                                                   unsigned long long b,
                                                   unsigned long long c) {
    unsigned long long d;
    asm("fma.rn.f32x2 %0, %1, %2, %3;" : "=l"(d) : "l"(a), "l"(b), "l"(c));
    return d;
}
__device__ __forceinline__ unsigned long long pack2(float x, float y) {
    unsigned long long d;
    asm("mov.b64 %0, {%1, %2};" : "=l"(d) : "f"(x), "f"(y));
    return d;
}
__device__ __forceinline__ void unpack2(unsigned long long v, float& x, float& y) {
    asm("mov.b64 {%0, %1}, %2;" : "=f"(x), "=f"(y) : "l"(v));
}

// ---------------------------------------------------------------------------
// Kernel 2: per batch, out[m][n] = relu( (A^T B)[m][n] * inv_s[m] * inv_d[n] )
//   A = src[b] as [C][S] (row stride S), B = dst[b] as [C][S]
//   Block tile 128x128, K-tile 16, 256 threads, 8x8 microtile (f32x2-packed).
// ---------------------------------------------------------------------------
__global__ void __launch_bounds__(256, 2)
corr_gemm_kernel(const float* __restrict__ src,
                 const float* __restrict__ dst,
                 float* __restrict__ out) {
    __shared__ float As[BK][BM];
    __shared__ float Bs[BK][BN];

    const int b  = blockIdx.z;
    const int m0 = blockIdx.y * BM;   // src pixel tile
    const int n0 = blockIdx.x * BN;   // dst pixel tile
    const float* A  = src + (size_t)b * CC * SS;
    const float* Bp = dst + (size_t)b * CC * SS;

    const int tid = threadIdx.x;
    const int tx  = tid & 15;   // 16 col-groups
    const int ty  = tid >> 4;   // 16 row-groups

    // 8 rows x 8 cols per thread; cols packed as 4 f32x2 pairs.
    // Col layout: {n0 + tx*4 + 0..3, n0 + 64 + tx*4 + 0..3}  (conflict-free LDS)
    unsigned long long acc[8][4];
#pragma unroll
    for (int i = 0; i < 8; ++i)
#pragma unroll
        for (int j = 0; j < 4; ++j) acc[i][j] = 0ULL;

    for (int kt = 0; kt < CC; kt += BK) {
        // Cooperative tile load: 2048 floats per tile = 512 float4; 2 per thread.
#pragma unroll
        for (int r = 0; r < 2; ++r) {
            int j  = tid + r * 256;        // float4 index in [0,512)
            int kk = j >> 5;               // row within K-tile (32 float4/row)
            int mm = (j & 31) << 2;        // col (float index)
            *(float4*)&As[kk][mm] =
                *(const float4*)&A[(size_t)(kt + kk) * SS + m0 + mm];
            *(float4*)&Bs[kk][mm] =
                *(const float4*)&Bp[(size_t)(kt + kk) * SS + n0 + mm];
        }
        __syncthreads();

#pragma unroll
        for (int k = 0; k < BK; ++k) {
            float4 a0 = *(const float4*)&As[k][ty * 8];
            float4 a1 = *(const float4*)&As[k][ty * 8 + 4];
            float4 b0 = *(const float4*)&Bs[k][tx * 4];
            float4 b1 = *(const float4*)&Bs[k][64 + tx * 4];

            unsigned long long bv[4];
            bv[0] = pack2(b0.x, b0.y);
            bv[1] = pack2(b0.z, b0.w);
            bv[2] = pack2(b1.x, b1.y);
            bv[3] = pack2(b1.z, b1.w);

            float av[8] = {a0.x, a0.y, a0.z, a0.w, a1.x, a1.y, a1.z, a1.w};
#pragma unroll
            for (int i = 0; i < 8; ++i) {
                unsigned long long a2 = pack2(av[i], av[i]);
#pragma unroll
                for (int j = 0; j < 4; ++j)
                    acc[i][j] = fma2(a2, bv[j], acc[i][j]);
            }
        }
        __syncthreads();
    }

    // Epilogue: scale by inverse norms, ReLU, vectorized store.
    float invd[8];
#pragma unroll
    for (int j = 0; j < 4; ++j)
        invd[j] = g_inv_dst[b * SS + n0 + tx * 4 + j];
#pragma unroll
    for (int j = 0; j < 4; ++j)
        invd[4 + j] = g_inv_dst[b * SS + n0 + 64 + tx * 4 + j];

#pragma unroll
    for (int i = 0; i < 8; ++i) {
        int m = m0 + ty * 8 + i;
        float invs = g_inv_src[b * SS + m];
        float v[8];
#pragma unroll
        for (int j = 0; j < 4; ++j) {
            float lo, hi;
            unpack2(acc[i][j], lo, hi);
            v[j * 2]     = lo;
            v[j * 2 + 1] = hi;
        }
        float4 r0, r1;
        r0.x = fmaxf(v[0] * invs * invd[0], 0.0f);
        r0.y = fmaxf(v[1] * invs * invd[1], 0.0f);
        r0.z = fmaxf(v[2] * invs * invd[2], 0.0f);
        r0.w = fmaxf(v[3] * invs * invd[3], 0.0f);
        r1.x = fmaxf(v[4] * invs * invd[4], 0.0f);
        r1.y = fmaxf(v[5] * invs * invd[5], 0.0f);
        r1.z = fmaxf(v[6] * invs * invd[6], 0.0f);
        r1.w = fmaxf(v[7] * invs * invd[7], 0.0f);

        float* orow = out + (size_t)b * SS * SS + (size_t)m * SS;
        *(float4*)&orow[n0 + tx * 4]      = r0;
        *(float4*)&orow[n0 + 64 + tx * 4] = r1;
    }
}

// ---------------------------------------------------------------------------
extern "C" void kernel_launch(void* const* d_in, const int* in_sizes, int n_in,
                              void* d_out, int out_size) {
    const float* src = (const float*)d_in[0];
    const float* dst = (const float*)d_in[1];
    float* out = (float*)d_out;

    // 1) inverse channel norms for src and dst
    int norm_threads = 2 * BB * SS;                 // 36864
    inv_norm_kernel<<<norm_threads / 256, 256>>>(src, dst);

    // 2) batched correlation GEMM + normalize + ReLU
    dim3 grid(SS / BN, SS / BM, BB);                // (18, 18, 8)
    corr_gemm_kernel<<<grid, 256>>>(src, dst, out);
}

// round 3
// speedup vs baseline: 1.3976x; 1.3976x over previous
#include <cuda_runtime.h>
#include <cuda_bf16.h>
#include <cstdint>

#define BB 8
#define CC 256
#define SS 2304

#define BM 128
#define BN 128
#define BKK 32
#define KITERS (CC / BKK)   // 8
#define NSTAGE 3

// Padded SMEM row: 32 bf16 = 64B data, padded to 80B for conflict-free ldmatrix
#define ROWB 80
#define TILE_BYTES (128 * ROWB)          // 10240
#define OFF_AH 0
#define OFF_AL TILE_BYTES
#define OFF_BH (2 * TILE_BYTES)
#define OFF_BL (3 * TILE_BYTES)
#define STG_BYTES (4 * TILE_BYTES)       // 40960
#define SMEM_TOTAL (NSTAGE * STG_BYTES)  // 122880

// ---------------- scratch (__device__ globals; no cudaMalloc allowed) ------
__device__ __nv_bfloat16 g_Ah[(size_t)BB * SS * CC];
__device__ __nv_bfloat16 g_Al[(size_t)BB * SS * CC];
__device__ __nv_bfloat16 g_Bh[(size_t)BB * SS * CC];
__device__ __nv_bfloat16 g_Bl[(size_t)BB * SS * CC];
__device__ float g_inv_src[BB * SS];
__device__ float g_inv_dst[BB * SS];

// ---------------- PTX helpers (base ISA only; no tcgen05 on compute_103) ---
__device__ __forceinline__ uint32_t smem_u32(const void* p) {
    uint32_t a;
    asm("{ .reg .u64 t; cvta.to.shared.u64 t, %1; cvt.u32.u64 %0, t; }"
        : "=r"(a) : "l"(p));
    return a;
}
__device__ __forceinline__ void cpasync16(uint32_t dst, const void* src) {
    asm volatile("cp.async.cg.shared.global [%0], [%1], 16;"
                 :: "r"(dst), "l"(src) : "memory");
}
#define CP_COMMIT() asm volatile("cp.async.commit_group;" ::: "memory")
#define CP_WAIT(n)  asm volatile("cp.async.wait_group %0;" :: "n"(n) : "memory")

__device__ __forceinline__ void ldsm_x4(uint32_t* r, uint32_t addr) {
    asm volatile("ldmatrix.sync.aligned.m8n8.x4.shared.b16 {%0,%1,%2,%3}, [%4];"
                 : "=r"(r[0]), "=r"(r[1]), "=r"(r[2]), "=r"(r[3]) : "r"(addr));
}
__device__ __forceinline__ void mma16816(float* d, const uint32_t* a,
                                         uint32_t b0, uint32_t b1) {
    asm volatile(
        "mma.sync.aligned.m16n8k16.row.col.f32.bf16.bf16.f32 "
        "{%0,%1,%2,%3}, {%4,%5,%6,%7}, {%8,%9}, {%0,%1,%2,%3};"
        : "+f"(d[0]), "+f"(d[1]), "+f"(d[2]), "+f"(d[3])
        : "r"(a[0]), "r"(a[1]), "r"(a[2]), "r"(a[3]), "r"(b0), "r"(b1));
}

// ---------------------------------------------------------------------------
// Kernel 1: inverse channel norms
// ---------------------------------------------------------------------------
__global__ void inv_norm_kernel(const float* __restrict__ src,
                                const float* __restrict__ dst) {
    int idx = blockIdx.x * blockDim.x + threadIdx.x;
    const int total = BB * SS;
    const float* base;
    float* outp;
    int i = idx;
    if (idx < total) { base = src; outp = g_inv_src; }
    else             { base = dst; outp = g_inv_dst; i -= total; }
    int b = i / SS;
    int s = i - b * SS;
    const float* p = base + (size_t)b * CC * SS + s;
    float acc = 0.0f;
#pragma unroll 8
    for (int c = 0; c < CC; ++c) {
        float v = p[(size_t)c * SS];
        acc = fmaf(v, v, acc);
    }
    outp[i] = rsqrtf(acc);
}

// ---------------------------------------------------------------------------
// Kernel 2: transpose + bf16 hi/lo split:  fp32 [B,C,S] -> bf16 [B,S,C] x2
// ---------------------------------------------------------------------------
__global__ void prep_kernel(const float* __restrict__ src,
                            const float* __restrict__ dst) {
    __shared__ float tile[32][33];
    int z = blockIdx.z;
    int b = z >> 1, which = z & 1;
    const float* in = which ? dst : src;
    __nv_bfloat16* oh = which ? g_Bh : g_Ah;
    __nv_bfloat16* ol = which ? g_Bl : g_Al;
    int c0 = blockIdx.y * 32, s0 = blockIdx.x * 32;
    int tx = threadIdx.x & 31, ty = threadIdx.x >> 5;

    const float* p = in + (size_t)b * CC * SS;
#pragma unroll
    for (int i = 0; i < 4; ++i)
        tile[ty + i * 8][tx] = p[(size_t)(c0 + ty + i * 8) * SS + s0 + tx];
    __syncthreads();
#pragma unroll
    for (int i = 0; i < 4; ++i) {
        int srow = ty + i * 8;
        float v = tile[tx][srow];
        __nv_bfloat16 h = __float2bfloat16(v);
        __nv_bfloat16 l = __float2bfloat16(v - __bfloat162float(h));
        size_t o = ((size_t)b * SS + s0 + srow) * CC + c0 + tx;
        oh[o] = h;
        ol[o] = l;
    }
}

// ---------------------------------------------------------------------------
// Kernel 3: HMMA GEMM. out[b][m][n] = relu(dot * inv_s[m] * inv_d[n])
//   CTA 128x128, BK=32, 8 warps (4m x 2n), warp tile 32x64.
//   3-way bf16 split (hh + hl + lh), fp32 accumulate.
// ---------------------------------------------------------------------------
__global__ void __launch_bounds__(256, 1)
corr_mma_kernel(float* __restrict__ out) {
    extern __shared__ char smem[];
    uint32_t sb = smem_u32(smem);

    const int tid  = threadIdx.x;
    const int lane = tid & 31;
    const int wid  = tid >> 5;
    const int b  = blockIdx.z;
    const int m0 = blockIdx.y * BM;
    const int n0 = blockIdx.x * BN;

    const char* gAh = (const char*)(g_Ah + (size_t)b * SS * CC);
    const char* gAl = (const char*)(g_Al + (size_t)b * SS * CC);
    const char* gBh = (const char*)(g_Bh + (size_t)b * SS * CC);
    const char* gBl = (const char*)(g_Bl + (size_t)b * SS * CC);

    // stage loader: 128 rows x 4 chunks(16B) per tile, 4 tiles, 2 ops/thread/tile
    auto load_stage = [&](int st, int kt) {
        uint32_t sbase = sb + (uint32_t)st * STG_BYTES;
        int c0 = kt * BKK;
#pragma unroll
        for (int i = 0; i < 2; ++i) {
            int u = tid + i * 256;
            int row = u >> 2;
            int ch  = u & 3;
            size_t goA = ((size_t)(m0 + row) * CC + c0) * 2 + ch * 16;
            size_t goB = ((size_t)(n0 + row) * CC + c0) * 2 + ch * 16;
            uint32_t so = (uint32_t)(row * ROWB + ch * 16);
            cpasync16(sbase + OFF_AH + so, gAh + goA);
            cpasync16(sbase + OFF_AL + so, gAl + goA);
            cpasync16(sbase + OFF_BH + so, gBh + goB);
            cpasync16(sbase + OFF_BL + so, gBl + goB);
        }
    };

    load_stage(0, 0); CP_COMMIT();
    load_stage(1, 1); CP_COMMIT();

    float acc[2][8][4];
#pragma unroll
    for (int i = 0; i < 2; ++i)
#pragma unroll
        for (int j = 0; j < 8; ++j)
#pragma unroll
            for (int k = 0; k < 4; ++k) acc[i][j][k] = 0.0f;

    const int wm = wid & 3;   // m strip (32 rows)
    const int wn = wid >> 2;  // n strip (64 cols)

    // ldmatrix lane addressing (byte offsets within a tile):
    // A x4: matrices [m0-7@c, m8-15@c, m0-7@c+1, m8-15@c+1]
    const uint32_t aOff = (uint32_t)((wm * 32 + (lane & 15)) * ROWB + (lane >> 4) * 16);
    // B x4: matrices [n0-7@c, n0-7@c+1, n8-15@c, n8-15@c+1]
    const uint32_t bRow = (uint32_t)(wn * 64 + (lane & 7) + ((lane >> 4) << 3));
    const uint32_t bOff = bRow * ROWB + ((lane >> 3) & 1) * 16;

    for (int kt = 0; kt < KITERS; ++kt) {
        CP_WAIT(1);
        __syncthreads();
        if (kt + 2 < KITERS) load_stage((kt + 2) % NSTAGE, kt + 2);
        CP_COMMIT();

        const uint32_t sbase = sb + (uint32_t)(kt % NSTAGE) * STG_BYTES;
#pragma unroll
        for (int ks = 0; ks < 2; ++ks) {
            const uint32_t koff = (uint32_t)ks * 32;   // 2 chunks of 16B per k16
            uint32_t ah[2][4], al[2][4];
#pragma unroll
            for (int mt = 0; mt < 2; ++mt) {
                uint32_t ra = aOff + (uint32_t)mt * 16 * ROWB + koff;
                ldsm_x4(ah[mt], sbase + OFF_AH + ra);
                ldsm_x4(al[mt], sbase + OFF_AL + ra);
            }
            uint32_t bh[4][4], bl[4][4];
#pragma unroll
            for (int p = 0; p < 4; ++p) {
                uint32_t rb = bOff + (uint32_t)p * 16 * ROWB + koff;
                ldsm_x4(bh[p], sbase + OFF_BH + rb);
                ldsm_x4(bl[p], sbase + OFF_BL + rb);
            }
#pragma unroll
            for (int mt = 0; mt < 2; ++mt) {
#pragma unroll
                for (int p = 0; p < 4; ++p) {
                    mma16816(acc[mt][2 * p],     ah[mt], bh[p][0], bh[p][1]);
                    mma16816(acc[mt][2 * p + 1], ah[mt], bh[p][2], bh[p][3]);
                    mma16816(acc[mt][2 * p],     ah[mt], bl[p][0], bl[p][1]);
                    mma16816(acc[mt][2 * p + 1], ah[mt], bl[p][2], bl[p][3]);
                    mma16816(acc[mt][2 * p],     al[mt], bh[p][0], bh[p][1]);
                    mma16816(acc[mt][2 * p + 1], al[mt], bh[p][2], bh[p][3]);
                }
            }
        }
    }

    // ---- epilogue: scale by inverse norms, ReLU, float2 stores
    const float* invd = &g_inv_dst[b * SS + n0];
#pragma unroll
    for (int mt = 0; mt < 2; ++mt) {
#pragma unroll
        for (int h = 0; h < 2; ++h) {
            int m = m0 + wm * 32 + mt * 16 + (lane >> 2) + h * 8;
            float invs = g_inv_src[b * SS + m];
            float* orow = out + ((size_t)b * SS + m) * SS + n0;
#pragma unroll
            for (int nt = 0; nt < 8; ++nt) {
                int n = wn * 64 + nt * 8 + (lane & 3) * 2;
                float d0 = acc[mt][nt][h * 2 + 0];
                float d1 = acc[mt][nt][h * 2 + 1];
                float2 o;
                o.x = fmaxf(d0 * invs * invd[n], 0.0f);
                o.y = fmaxf(d1 * invs * invd[n + 1], 0.0f);
                *(float2*)&orow[n] = o;
            }
        }
    }
}

// ---------------------------------------------------------------------------
extern "C" void kernel_launch(void* const* d_in, const int* in_sizes, int n_in,
                              void* d_out, int out_size) {
    const float* src = (const float*)d_in[0];
    const float* dst = (const float*)d_in[1];
    float* out = (float*)d_out;

    cudaFuncSetAttribute(corr_mma_kernel,
                         cudaFuncAttributeMaxDynamicSharedMemorySize, SMEM_TOTAL);

    inv_norm_kernel<<<2 * BB * SS / 256, 256>>>(src, dst);
    prep_kernel<<<dim3(SS / 32, CC / 32, 2 * BB), 256>>>(src, dst);
    corr_mma_kernel<<<dim3(SS / BN, SS / BM, BB), 256, SMEM_TOTAL>>>(out);
}

// round 4
// speedup vs baseline: 1.7124x; 1.2253x over previous
#include <cuda_runtime.h>
#include <cuda_bf16.h>
#include <cstdint>

#define BB 8
#define CC 256
#define SS 2304

#define BM 128
#define BN 256
#define BKK 32
#define KITERS (CC / BKK)   // 8
#define NSTAGE 3

// Padded SMEM row: 32 bf16 = 64B data, padded to 80B (conflict-free ldmatrix)
#define ROWB 80
#define A_TILE (BM * ROWB)               // 10240
#define B_TILE (BN * ROWB)               // 20480
#define OFF_AH 0
#define OFF_AL A_TILE
#define OFF_BH (2 * A_TILE)
#define OFF_BL (2 * A_TILE + B_TILE)
#define STG_BYTES (2 * A_TILE + 2 * B_TILE)   // 61440
#define SMEM_TOTAL (NSTAGE * STG_BYTES)       // 184320

// ---------------- scratch (__device__ globals; no cudaMalloc allowed) ------
__device__ __nv_bfloat16 g_Ah[(size_t)BB * SS * CC];
__device__ __nv_bfloat16 g_Al[(size_t)BB * SS * CC];
__device__ __nv_bfloat16 g_Bh[(size_t)BB * SS * CC];
__device__ __nv_bfloat16 g_Bl[(size_t)BB * SS * CC];
__device__ float g_part[2][8][BB * SS];   // per-32ch partial sum of squares
__device__ float g_inv_src[BB * SS];
__device__ float g_inv_dst[BB * SS];

// ---------------- PTX helpers (base ISA only) -------------------------------
__device__ __forceinline__ uint32_t smem_u32(const void* p) {
    uint32_t a;
    asm("{ .reg .u64 t; cvta.to.shared.u64 t, %1; cvt.u32.u64 %0, t; }"
        : "=r"(a) : "l"(p));
    return a;
}
__device__ __forceinline__ void cpasync16(uint32_t dst, const void* src) {
    asm volatile("cp.async.cg.shared.global [%0], [%1], 16;"
                 :: "r"(dst), "l"(src) : "memory");
}
#define CP_COMMIT() asm volatile("cp.async.commit_group;" ::: "memory")
#define CP_WAIT(n)  asm volatile("cp.async.wait_group %0;" :: "n"(n) : "memory")

__device__ __forceinline__ void ldsm_x4(uint32_t* r, uint32_t addr) {
    asm volatile("ldmatrix.sync.aligned.m8n8.x4.shared.b16 {%0,%1,%2,%3}, [%4];"
                 : "=r"(r[0]), "=r"(r[1]), "=r"(r[2]), "=r"(r[3]) : "r"(addr));
}
__device__ __forceinline__ void mma16816(float* d, const uint32_t* a,
                                         uint32_t b0, uint32_t b1) {
    asm volatile(
        "mma.sync.aligned.m16n8k16.row.col.f32.bf16.bf16.f32 "
        "{%0,%1,%2,%3}, {%4,%5,%6,%7}, {%8,%9}, {%0,%1,%2,%3};"
        : "+f"(d[0]), "+f"(d[1]), "+f"(d[2]), "+f"(d[3])
        : "r"(a[0]), "r"(a[1]), "r"(a[2]), "r"(a[3]), "r"(b0), "r"(b1));
}

// ---------------------------------------------------------------------------
// Kernel 1: transpose + bf16 hi/lo split + fused partial sum of squares
//   fp32 [B,C,S] -> bf16 [B,S,C] x2 ; g_part[which][cblk][b*S+s]
// ---------------------------------------------------------------------------
__global__ void prep_kernel(const float* __restrict__ src,
                            const float* __restrict__ dst) {
    __shared__ float tile[32][33];
    int z = blockIdx.z;
    int b = z >> 1, which = z & 1;
    const float* in = which ? dst : src;
    __nv_bfloat16* oh = which ? g_Bh : g_Ah;
    __nv_bfloat16* ol = which ? g_Bl : g_Al;
    int c0 = blockIdx.y * 32, s0 = blockIdx.x * 32;
    int tx = threadIdx.x & 31, ty = threadIdx.x >> 5;

    const float* p = in + (size_t)b * CC * SS;
#pragma unroll
    for (int i = 0; i < 4; ++i)
        tile[ty + i * 8][tx] = p[(size_t)(c0 + ty + i * 8) * SS + s0 + tx];
    __syncthreads();
#pragma unroll
    for (int i = 0; i < 4; ++i) {
        int srow = ty + i * 8;                 // s index within block
        float v = tile[tx][srow];              // lane tx holds channel c0+tx
        __nv_bfloat16 h = __float2bfloat16(v);
        __nv_bfloat16 l = __float2bfloat16(v - __bfloat162float(h));
        size_t o = ((size_t)b * SS + s0 + srow) * CC + c0 + tx;
        oh[o] = h;
        ol[o] = l;
        // fused 32-channel partial sum of squares (warp reduce over lanes)
        float sq = v * v;
#pragma unroll
        for (int off = 16; off >= 1; off >>= 1)
            sq += __shfl_xor_sync(0xffffffffu, sq, off);
        if (tx == 0)
            g_part[which][blockIdx.y][b * SS + s0 + srow] = sq;
    }
}

// ---------------------------------------------------------------------------
// Kernel 2: combine partials -> inverse norms
// ---------------------------------------------------------------------------
__global__ void combine_kernel() {
    int idx = blockIdx.x * blockDim.x + threadIdx.x;   // 2*BB*SS threads
    const int total = BB * SS;
    int which = (idx >= total) ? 1 : 0;
    int i = idx - which * total;
    float s = 0.0f;
#pragma unroll
    for (int cb = 0; cb < 8; ++cb) s += g_part[which][cb][i];
    float r = rsqrtf(s);
    if (which) g_inv_dst[i] = r; else g_inv_src[i] = r;
}

// ---------------------------------------------------------------------------
// Kernel 3: HMMA GEMM. out[b][m][n] = relu(dot * inv_s[m] * inv_d[n])
//   CTA 128x256, BK=32, 3-stage cp.async. 8 warps (2m x 4n), warp tile 64x64.
//   3-way bf16 split (hh + hl + lh), fp32 accumulate.
// ---------------------------------------------------------------------------
__global__ void __launch_bounds__(256, 1)
corr_mma_kernel(float* __restrict__ out) {
    extern __shared__ char smem[];
    uint32_t sb = smem_u32(smem);

    const int tid  = threadIdx.x;
    const int lane = tid & 31;
    const int wid  = tid >> 5;
    const int b  = blockIdx.z;
    const int m0 = blockIdx.y * BM;
    const int n0 = blockIdx.x * BN;

    const char* gAh = (const char*)(g_Ah + (size_t)b * SS * CC);
    const char* gAl = (const char*)(g_Al + (size_t)b * SS * CC);
    const char* gBh = (const char*)(g_Bh + (size_t)b * SS * CC);
    const char* gBl = (const char*)(g_Bl + (size_t)b * SS * CC);

    // Stage loader: A 128 rows + B 256 rows, 4x16B chunks per row, hi+lo.
    // 1536 pair-units, 6 per thread, 2 cp.async per unit -> 12 cp/thread.
    auto load_stage = [&](int st, int kt) {
        uint32_t sbase = sb + (uint32_t)st * STG_BYTES;
        int c0 = kt * BKK;
#pragma unroll
        for (int i = 0; i < 6; ++i) {
            int u = tid + i * 256;
            if (u < 512) {                       // A rows
                int row = u >> 2, ch = u & 3;
                size_t go = ((size_t)(m0 + row) * CC + c0) * 2 + ch * 16;
                uint32_t so = (uint32_t)(row * ROWB + ch * 16);
                cpasync16(sbase + OFF_AH + so, gAh + go);
                cpasync16(sbase + OFF_AL + so, gAl + go);
            } else {                             // B rows
                int v2 = u - 512;
                int row = v2 >> 2, ch = v2 & 3;
                size_t go = ((size_t)(n0 + row) * CC + c0) * 2 + ch * 16;
                uint32_t so = (uint32_t)(row * ROWB + ch * 16);
                cpasync16(sbase + OFF_BH + so, gBh + go);
                cpasync16(sbase + OFF_BL + so, gBl + go);
            }
        }
    };

    load_stage(0, 0); CP_COMMIT();
    load_stage(1, 1); CP_COMMIT();

    float acc[4][8][4];
#pragma unroll
    for (int i = 0; i < 4; ++i)
#pragma unroll
        for (int j = 0; j < 8; ++j)
#pragma unroll
            for (int k = 0; k < 4; ++k) acc[i][j][k] = 0.0f;

    const int wn = wid & 3;    // n strip (64 cols)
    const int wm = wid >> 2;   // m strip (64 rows)

    // ldmatrix lane addressing (byte offsets within a tile):
    const uint32_t aOff = (uint32_t)((wm * 64 + (lane & 15)) * ROWB + (lane >> 4) * 16);
    const uint32_t bRow = (uint32_t)(wn * 64 + (lane & 7) + ((lane >> 4) << 3));
    const uint32_t bOff = bRow * ROWB + ((lane >> 3) & 1) * 16;

    for (int kt = 0; kt < KITERS; ++kt) {
        CP_WAIT(1);
        __syncthreads();
        if (kt + 2 < KITERS) load_stage((kt + 2) % NSTAGE, kt + 2);
        CP_COMMIT();

        const uint32_t sbase = sb + (uint32_t)(kt % NSTAGE) * STG_BYTES;
#pragma unroll
        for (int ks = 0; ks < 2; ++ks) {
            const uint32_t koff = (uint32_t)ks * 32;   // k16 = 32 bytes

            uint32_t a[4][4], b1[4][4], b2[4][4];
#pragma unroll
            for (int mt = 0; mt < 4; ++mt)
                ldsm_x4(a[mt], sbase + OFF_AH + aOff + (uint32_t)mt * 16 * ROWB + koff);
#pragma unroll
            for (int p = 0; p < 4; ++p)
                ldsm_x4(b1[p], sbase + OFF_BH + bOff + (uint32_t)p * 16 * ROWB + koff);
            // pass 1: Ah * Bh
#pragma unroll
            for (int mt = 0; mt < 4; ++mt)
#pragma unroll
                for (int p = 0; p < 4; ++p) {
                    mma16816(acc[mt][2 * p],     a[mt], b1[p][0], b1[p][1]);
                    mma16816(acc[mt][2 * p + 1], a[mt], b1[p][2], b1[p][3]);
                }
#pragma unroll
            for (int p = 0; p < 4; ++p)
                ldsm_x4(b2[p], sbase + OFF_BL + bOff + (uint32_t)p * 16 * ROWB + koff);
            // pass 2: Ah * Bl
#pragma unroll
            for (int mt = 0; mt < 4; ++mt)
#pragma unroll
                for (int p = 0; p < 4; ++p) {
                    mma16816(acc[mt][2 * p],     a[mt], b2[p][0], b2[p][1]);
                    mma16816(acc[mt][2 * p + 1], a[mt], b2[p][2], b2[p][3]);
                }
#pragma unroll
            for (int mt = 0; mt < 4; ++mt)
                ldsm_x4(a[mt], sbase + OFF_AL + aOff + (uint32_t)mt * 16 * ROWB + koff);
            // pass 3: Al * Bh
#pragma unroll
            for (int mt = 0; mt < 4; ++mt)
#pragma unroll
                for (int p = 0; p < 4; ++p) {
                    mma16816(acc[mt][2 * p],     a[mt], b1[p][0], b1[p][1]);
                    mma16816(acc[mt][2 * p + 1], a[mt], b1[p][2], b1[p][3]);
                }
        }
    }

    // ---- epilogue: scale by inverse norms, ReLU, float2 stores
    const float* invd = &g_inv_dst[b * SS + n0];
#pragma unroll
    for (int mt = 0; mt < 4; ++mt) {
#pragma unroll
        for (int h = 0; h < 2; ++h) {
            int m = m0 + wm * 64 + mt * 16 + (lane >> 2) + h * 8;
            float invs = g_inv_src[b * SS + m];
            float* orow = out + ((size_t)b * SS + m) * SS + n0;
#pragma unroll
            for (int nt = 0; nt < 8; ++nt) {
                int n = wn * 64 + nt * 8 + (lane & 3) * 2;
                float2 o;
                o.x = fmaxf(acc[mt][nt][h * 2 + 0] * invs * invd[n], 0.0f);
                o.y = fmaxf(acc[mt][nt][h * 2 + 1] * invs * invd[n + 1], 0.0f);
                *(float2*)&orow[n] = o;
            }
        }
    }
}

// ---------------------------------------------------------------------------
extern "C" void kernel_launch(void* const* d_in, const int* in_sizes, int n_in,
                              void* d_out, int out_size) {
    const float* src = (const float*)d_in[0];
    const float* dst = (const float*)d_in[1];
    float* out = (float*)d_out;

    cudaFuncSetAttribute(corr_mma_kernel,
                         cudaFuncAttributeMaxDynamicSharedMemorySize, SMEM_TOTAL);

    prep_kernel<<<dim3(SS / 32, CC / 32, 2 * BB), 256>>>(src, dst);
    combine_kernel<<<2 * BB * SS / 256, 256>>>();
    corr_mma_kernel<<<dim3(SS / BN, SS / BM, BB), 256, SMEM_TOTAL>>>(out);
}

// round 5
// speedup vs baseline: 2.2005x; 1.2850x over previous
#include <cuda_runtime.h>
#include <cuda_fp16.h>
#include <cstdint>

#define BB 8
#define CC 256
#define SS 2304

#define BM 128
#define BN 256
#define BKK 32
#define KITERS (CC / BKK)   // 8
#define NSTAGE 4

// Padded SMEM row: 32 fp16 = 64B data, padded to 80B (conflict-free ldmatrix)
#define ROWB 80
#define A_TILE (BM * ROWB)               // 10240
#define B_TILE (BN * ROWB)               // 20480
#define OFF_AH 0
#define OFF_AL A_TILE
#define OFF_BH (2 * A_TILE)
#define STG_BYTES (2 * A_TILE + B_TILE)       // 40960
#define SMEM_TOTAL (NSTAGE * STG_BYTES)       // 163840

// ---------------- scratch (__device__ globals; no cudaMalloc allowed) ------
__device__ __half g_Ah[(size_t)BB * SS * CC];
__device__ __half g_Al[(size_t)BB * SS * CC];
__device__ __half g_Bh[(size_t)BB * SS * CC];
__device__ float g_part[2][8][BB * SS];   // per-32ch partial sum of squares
__device__ float g_inv_src[BB * SS];
__device__ float g_inv_dst[BB * SS];

// ---------------- PTX helpers (base ISA only) -------------------------------
__device__ __forceinline__ uint32_t smem_u32(const void* p) {
    uint32_t a;
    asm("{ .reg .u64 t; cvta.to.shared.u64 t, %1; cvt.u32.u64 %0, t; }"
        : "=r"(a) : "l"(p));
    return a;
}
__device__ __forceinline__ void cpasync16(uint32_t dst, const void* src) {
    asm volatile("cp.async.cg.shared.global [%0], [%1], 16;"
                 :: "r"(dst), "l"(src) : "memory");
}
#define CP_COMMIT() asm volatile("cp.async.commit_group;" ::: "memory")
#define CP_WAIT(n)  asm volatile("cp.async.wait_group %0;" :: "n"(n) : "memory")

__device__ __forceinline__ void ldsm_x4(uint32_t* r, uint32_t addr) {
    asm volatile("ldmatrix.sync.aligned.m8n8.x4.shared.b16 {%0,%1,%2,%3}, [%4];"
                 : "=r"(r[0]), "=r"(r[1]), "=r"(r[2]), "=r"(r[3]) : "r"(addr));
}
__device__ __forceinline__ void mma16816(float* d, const uint32_t* a,
                                         uint32_t b0, uint32_t b1) {
    asm volatile(
        "mma.sync.aligned.m16n8k16.row.col.f32.f16.f16.f32 "
        "{%0,%1,%2,%3}, {%4,%5,%6,%7}, {%8,%9}, {%0,%1,%2,%3};"
        : "+f"(d[0]), "+f"(d[1]), "+f"(d[2]), "+f"(d[3])
        : "r"(a[0]), "r"(a[1]), "r"(a[2]), "r"(a[3]), "r"(b0), "r"(b1));
}

// ---------------------------------------------------------------------------
// Kernel 1: transpose + fp16 split + fused partial sum of squares
//   src: fp32 [B,C,S] -> fp16 hi+lo [B,S,C]; dst: -> fp16 hi only
// ---------------------------------------------------------------------------
__global__ void prep_kernel(const float* __restrict__ src,
                            const float* __restrict__ dst) {
    __shared__ float tile[32][33];
    int z = blockIdx.z;
    int b = z >> 1, which = z & 1;
    const float* in = which ? dst : src;
    int c0 = blockIdx.y * 32, s0 = blockIdx.x * 32;
    int tx = threadIdx.x & 31, ty = threadIdx.x >> 5;

    const float* p = in + (size_t)b * CC * SS;
#pragma unroll
    for (int i = 0; i < 4; ++i)
        tile[ty + i * 8][tx] = p[(size_t)(c0 + ty + i * 8) * SS + s0 + tx];
    __syncthreads();
#pragma unroll
    for (int i = 0; i < 4; ++i) {
        int srow = ty + i * 8;                 // s index within block
        float v = tile[tx][srow];              // lane tx holds channel c0+tx
        size_t o = ((size_t)b * SS + s0 + srow) * CC + c0 + tx;
        __half h = __float2half_rn(v);
        if (which) {
            g_Bh[o] = h;
        } else {
            g_Ah[o] = h;
            g_Al[o] = __float2half_rn(v - __half2float(h));
        }
        // fused 32-channel partial sum of squares (warp reduce over lanes)
        float sq = v * v;
#pragma unroll
        for (int off = 16; off >= 1; off >>= 1)
            sq += __shfl_xor_sync(0xffffffffu, sq, off);
        if (tx == 0)
            g_part[which][blockIdx.y][b * SS + s0 + srow] = sq;
    }
}

// ---------------------------------------------------------------------------
// Kernel 2: combine partials -> inverse norms
// ---------------------------------------------------------------------------
__global__ void combine_kernel() {
    int idx = blockIdx.x * blockDim.x + threadIdx.x;   // 2*BB*SS threads
    const int total = BB * SS;
    int which = (idx >= total) ? 1 : 0;
    int i = idx - which * total;
    float s = 0.0f;
#pragma unroll
    for (int cb = 0; cb < 8; ++cb) s += g_part[which][cb][i];
    float r = rsqrtf(s);
    if (which) g_inv_dst[i] = r; else g_inv_src[i] = r;
}

// ---------------------------------------------------------------------------
// Kernel 3: HMMA GEMM. out[b][m][n] = relu(dot * inv_s[m] * inv_d[n])
//   CTA 128x256, BK=32, 4-stage cp.async. 8 warps (2m x 4n), warp tile 64x64.
//   Asymmetric fp16 split: (Ah + Al) * Bh, fp32 accumulate, 2 MMA passes.
// ---------------------------------------------------------------------------
__global__ void __launch_bounds__(256, 1)
corr_mma_kernel(float* __restrict__ out) {
    extern __shared__ char smem[];
    uint32_t sb = smem_u32(smem);

    const int tid  = threadIdx.x;
    const int lane = tid & 31;
    const int wid  = tid >> 5;
    const int b  = blockIdx.z;
    const int m0 = blockIdx.y * BM;
    const int n0 = blockIdx.x * BN;

    const char* gAh = (const char*)(g_Ah + (size_t)b * SS * CC);
    const char* gAl = (const char*)(g_Al + (size_t)b * SS * CC);
    const char* gBh = (const char*)(g_Bh + (size_t)b * SS * CC);

    // Stage loader: A 128 rows (hi+lo) + B 256 rows (hi), 4x16B chunks per row.
    // cp.async per thread: 2 iters * 2 (A) + 4 iters * 1 (B) = 8.
    auto load_stage = [&](int st, int kt) {
        uint32_t sbase = sb + (uint32_t)st * STG_BYTES;
        int c0 = kt * BKK;
#pragma unroll
        for (int i = 0; i < 2; ++i) {
            int u = tid + i * 256;             // [0,512): A rows
            int row = u >> 2, ch = u & 3;
            size_t go = ((size_t)(m0 + row) * CC + c0) * 2 + ch * 16;
            uint32_t so = (uint32_t)(row * ROWB + ch * 16);
            cpasync16(sbase + OFF_AH + so, gAh + go);
            cpasync16(sbase + OFF_AL + so, gAl + go);
        }
#pragma unroll
        for (int i = 0; i < 4; ++i) {
            int u = tid + i * 256;             // [0,1024): B rows
            int row = u >> 2, ch = u & 3;
            size_t go = ((size_t)(n0 + row) * CC + c0) * 2 + ch * 16;
            uint32_t so = (uint32_t)(row * ROWB + ch * 16);
            cpasync16(sbase + OFF_BH + so, gBh + go);
        }
    };

    load_stage(0, 0); CP_COMMIT();
    load_stage(1, 1); CP_COMMIT();
    load_stage(2, 2); CP_COMMIT();

    float acc[4][8][4];
#pragma unroll
    for (int i = 0; i < 4; ++i)
#pragma unroll
        for (int j = 0; j < 8; ++j)
#pragma unroll
            for (int k = 0; k < 4; ++k) acc[i][j][k] = 0.0f;

    const int wn = wid & 3;    // n strip (64 cols)
    const int wm = wid >> 2;   // m strip (64 rows)

    // ldmatrix lane addressing (byte offsets within a tile):
    const uint32_t aOff = (uint32_t)((wm * 64 + (lane & 15)) * ROWB + (lane >> 4) * 16);
    const uint32_t bRow = (uint32_t)(wn * 64 + (lane & 7) + ((lane >> 4) << 3));
    const uint32_t bOff = bRow * ROWB + ((lane >> 3) & 1) * 16;

    for (int kt = 0; kt < KITERS; ++kt) {
        CP_WAIT(2);
        __syncthreads();
        if (kt + 3 < KITERS) load_stage((kt + 3) % NSTAGE, kt + 3);
        CP_COMMIT();

        const uint32_t sbase = sb + (uint32_t)(kt % NSTAGE) * STG_BYTES;
#pragma unroll
        for (int ks = 0; ks < 2; ++ks) {
            const uint32_t koff = (uint32_t)ks * 32;   // k16 = 32 bytes

            uint32_t a[4][4], bh[4][4];
#pragma unroll
            for (int mt = 0; mt < 4; ++mt)
                ldsm_x4(a[mt], sbase + OFF_AH + aOff + (uint32_t)mt * 16 * ROWB + koff);
#pragma unroll
            for (int p = 0; p < 4; ++p)
                ldsm_x4(bh[p], sbase + OFF_BH + bOff + (uint32_t)p * 16 * ROWB + koff);
            // pass 1: Ah * Bh
#pragma unroll
            for (int mt = 0; mt < 4; ++mt)
#pragma unroll
                for (int p = 0; p < 4; ++p) {
                    mma16816(acc[mt][2 * p],     a[mt], bh[p][0], bh[p][1]);
                    mma16816(acc[mt][2 * p + 1], a[mt], bh[p][2], bh[p][3]);
                }
            // pass 2: Al * Bh (reload A frags from lo tile; B frags reused)
#pragma unroll
            for (int mt = 0; mt < 4; ++mt)
                ldsm_x4(a[mt], sbase + OFF_AL + aOff + (uint32_t)mt * 16 * ROWB + koff);
#pragma unroll
            for (int mt = 0; mt < 4; ++mt)
#pragma unroll
                for (int p = 0; p < 4; ++p) {
                    mma16816(acc[mt][2 * p],     a[mt], bh[p][0], bh[p][1]);
                    mma16816(acc[mt][2 * p + 1], a[mt], bh[p][2], bh[p][3]);
                }
        }
    }

    // ---- epilogue: scale by inverse norms, ReLU, float2 stores
    const float* invd = &g_inv_dst[b * SS + n0];
#pragma unroll
    for (int mt = 0; mt < 4; ++mt) {
#pragma unroll
        for (int h = 0; h < 2; ++h) {
            int m = m0 + wm * 64 + mt * 16 + (lane >> 2) + h * 8;
            float invs = g_inv_src[b * SS + m];
            float* orow = out + ((size_t)b * SS + m) * SS + n0;
#pragma unroll
            for (int nt = 0; nt < 8; ++nt) {
                int n = wn * 64 + nt * 8 + (lane & 3) * 2;
                float2 o;
                o.x = fmaxf(acc[mt][nt][h * 2 + 0] * invs * invd[n], 0.0f);
                o.y = fmaxf(acc[mt][nt][h * 2 + 1] * invs * invd[n + 1], 0.0f);
                *(float2*)&orow[n] = o;
            }
        }
    }
}

// ---------------------------------------------------------------------------
extern "C" void kernel_launch(void* const* d_in, const int* in_sizes, int n_in,
                              void* d_out, int out_size) {
    const float* src = (const float*)d_in[0];
    const float* dst = (const float*)d_in[1];
    float* out = (float*)d_out;

    cudaFuncSetAttribute(corr_mma_kernel,
                         cudaFuncAttributeMaxDynamicSharedMemorySize, SMEM_TOTAL);

    prep_kernel<<<dim3(SS / 32, CC / 32, 2 * BB), 256>>>(src, dst);
    combine_kernel<<<2 * BB * SS / 256, 256>>>();
    corr_mma_kernel<<<dim3(SS / BN, SS / BM, BB), 256, SMEM_TOTAL>>>(out);
}

// round 6
// speedup vs baseline: 2.9077x; 1.3214x over previous
#include <cuda_runtime.h>
#include <cuda_fp16.h>
#include <cstdint>

#define BB 8
#define CC 256
#define SS 2304

#define BM 128
#define BN 256
#define BKK 32
#define KITERS (CC / BKK)   // 8
#define NSTAGE 5

// Padded SMEM row: 32 fp16 = 64B data, padded to 80B (conflict-free ldmatrix)
#define ROWB 80
#define A_TILE (BM * ROWB)               // 10240
#define B_TILE (BN * ROWB)               // 20480
#define OFF_A 0
#define OFF_B A_TILE
#define STG_BYTES (A_TILE + B_TILE)           // 30720
#define SMEM_TOTAL (NSTAGE * STG_BYTES)       // 153600

// ---------------- scratch (__device__ globals; no cudaMalloc allowed) ------
__device__ __half g_A[(size_t)BB * SS * CC];
__device__ __half g_B[(size_t)BB * SS * CC];
__device__ float g_part[2][8][BB * SS];   // per-32ch partial sum of squares
__device__ float g_inv_src[BB * SS];
__device__ float g_inv_dst[BB * SS];

// ---------------- PTX helpers (base ISA only) -------------------------------
__device__ __forceinline__ uint32_t smem_u32(const void* p) {
    uint32_t a;
    asm("{ .reg .u64 t; cvta.to.shared.u64 t, %1; cvt.u32.u64 %0, t; }"
        : "=r"(a) : "l"(p));
    return a;
}
__device__ __forceinline__ void cpasync16(uint32_t dst, const void* src) {
    asm volatile("cp.async.cg.shared.global [%0], [%1], 16;"
                 :: "r"(dst), "l"(src) : "memory");
}
#define CP_COMMIT() asm volatile("cp.async.commit_group;" ::: "memory")
#define CP_WAIT(n)  asm volatile("cp.async.wait_group %0;" :: "n"(n) : "memory")

__device__ __forceinline__ void ldsm_x4(uint32_t* r, uint32_t addr) {
    asm volatile("ldmatrix.sync.aligned.m8n8.x4.shared.b16 {%0,%1,%2,%3}, [%4];"
                 : "=r"(r[0]), "=r"(r[1]), "=r"(r[2]), "=r"(r[3]) : "r"(addr));
}
__device__ __forceinline__ void mma16816(float* d, const uint32_t* a,
                                         uint32_t b0, uint32_t b1) {
    asm volatile(
        "mma.sync.aligned.m16n8k16.row.col.f32.f16.f16.f32 "
        "{%0,%1,%2,%3}, {%4,%5,%6,%7}, {%8,%9}, {%0,%1,%2,%3};"
        : "+f"(d[0]), "+f"(d[1]), "+f"(d[2]), "+f"(d[3])
        : "r"(a[0]), "r"(a[1]), "r"(a[2]), "r"(a[3]), "r"(b0), "r"(b1));
}

// ---------------------------------------------------------------------------
// Kernel 1: transpose + fp16 convert + fused partial sum of squares
//   fp32 [B,C,S] -> fp16 [B,S,C]; partials g_part[which][cblk][b*S+s]
// ---------------------------------------------------------------------------
__global__ void prep_kernel(const float* __restrict__ src,
                            const float* __restrict__ dst) {
    __shared__ float tile[32][33];
    int z = blockIdx.z;
    int b = z >> 1, which = z & 1;
    const float* in = which ? dst : src;
    __half* outp = which ? g_B : g_A;
    int c0 = blockIdx.y * 32, s0 = blockIdx.x * 32;
    int tx = threadIdx.x & 31, ty = threadIdx.x >> 5;

    const float* p = in + (size_t)b * CC * SS;
#pragma unroll
    for (int i = 0; i < 4; ++i)
        tile[ty + i * 8][tx] = p[(size_t)(c0 + ty + i * 8) * SS + s0 + tx];
    __syncthreads();
#pragma unroll
    for (int i = 0; i < 4; ++i) {
        int srow = ty + i * 8;                 // s index within block
        float v = tile[tx][srow];              // lane tx holds channel c0+tx
        outp[((size_t)b * SS + s0 + srow) * CC + c0 + tx] = __float2half_rn(v);
        // fused 32-channel partial sum of squares (warp reduce over lanes)
        float sq = v * v;
#pragma unroll
        for (int off = 16; off >= 1; off >>= 1)
            sq += __shfl_xor_sync(0xffffffffu, sq, off);
        if (tx == 0)
            g_part[which][blockIdx.y][b * SS + s0 + srow] = sq;
    }
}

// ---------------------------------------------------------------------------
// Kernel 2: combine partials -> inverse norms
// ---------------------------------------------------------------------------
__global__ void combine_kernel() {
    int idx = blockIdx.x * blockDim.x + threadIdx.x;   // 2*BB*SS threads
    const int total = BB * SS;
    int which = (idx >= total) ? 1 : 0;
    int i = idx - which * total;
    float s = 0.0f;
#pragma unroll
    for (int cb = 0; cb < 8; ++cb) s += g_part[which][cb][i];
    float r = rsqrtf(s);
    if (which) g_inv_dst[i] = r; else g_inv_src[i] = r;
}

// ---------------------------------------------------------------------------
// Kernel 3: HMMA GEMM. out[b][m][n] = relu(dot * inv_s[m] * inv_d[n])
//   CTA 128x256, BK=32, 5-stage cp.async. 8 warps (2m x 4n), warp tile 64x64.
//   Plain fp16 x fp16, fp32 accumulate (single pass).
// ---------------------------------------------------------------------------
__global__ void __launch_bounds__(256, 1)
corr_mma_kernel(float* __restrict__ out) {
    extern __shared__ char smem[];
    uint32_t sb = smem_u32(smem);

    const int tid  = threadIdx.x;
    const int lane = tid & 31;
    const int wid  = tid >> 5;
    const int b  = blockIdx.z;
    const int m0 = blockIdx.y * BM;
    const int n0 = blockIdx.x * BN;

    const char* gA = (const char*)(g_A + (size_t)b * SS * CC);
    const char* gB = (const char*)(g_B + (size_t)b * SS * CC);

    // Stage loader: A 128 rows + B 256 rows, 4x16B chunks per row.
    // cp.async per thread: 2 (A) + 4 (B) = 6.
    auto load_stage = [&](int st, int kt) {
        uint32_t sbase = sb + (uint32_t)st * STG_BYTES;
        int c0 = kt * BKK;
#pragma unroll
        for (int i = 0; i < 2; ++i) {
            int u = tid + i * 256;             // [0,512): A rows
            int row = u >> 2, ch = u & 3;
            size_t go = ((size_t)(m0 + row) * CC + c0) * 2 + ch * 16;
            cpasync16(sbase + OFF_A + (uint32_t)(row * ROWB + ch * 16), gA + go);
        }
#pragma unroll
        for (int i = 0; i < 4; ++i) {
            int u = tid + i * 256;             // [0,1024): B rows
            int row = u >> 2, ch = u & 3;
            size_t go = ((size_t)(n0 + row) * CC + c0) * 2 + ch * 16;
            cpasync16(sbase + OFF_B + (uint32_t)(row * ROWB + ch * 16), gB + go);
        }
    };

    load_stage(0, 0); CP_COMMIT();
    load_stage(1, 1); CP_COMMIT();
    load_stage(2, 2); CP_COMMIT();
    load_stage(3, 3); CP_COMMIT();

    float acc[4][8][4];
#pragma unroll
    for (int i = 0; i < 4; ++i)
#pragma unroll
        for (int j = 0; j < 8; ++j)
#pragma unroll
            for (int k = 0; k < 4; ++k) acc[i][j][k] = 0.0f;

    const int wn = wid & 3;    // n strip (64 cols)
    const int wm = wid >> 2;   // m strip (64 rows)

    // ldmatrix lane addressing (byte offsets within a tile):
    const uint32_t aOff = (uint32_t)((wm * 64 + (lane & 15)) * ROWB + (lane >> 4) * 16);
    const uint32_t bRow = (uint32_t)(wn * 64 + (lane & 7) + ((lane >> 4) << 3));
    const uint32_t bOff = bRow * ROWB + ((lane >> 3) & 1) * 16;

    for (int kt = 0; kt < KITERS; ++kt) {
        CP_WAIT(3);
        __syncthreads();
        if (kt + 4 < KITERS) load_stage((kt + 4) % NSTAGE, kt + 4);
        CP_COMMIT();

        const uint32_t sbase = sb + (uint32_t)(kt % NSTAGE) * STG_BYTES;
#pragma unroll
        for (int ks = 0; ks < 2; ++ks) {
            const uint32_t koff = (uint32_t)ks * 32;   // k16 = 32 bytes

            uint32_t a[4][4], bh[4][4];
#pragma unroll
            for (int mt = 0; mt < 4; ++mt)
                ldsm_x4(a[mt], sbase + OFF_A + aOff + (uint32_t)mt * 16 * ROWB + koff);
#pragma unroll
            for (int p = 0; p < 4; ++p)
                ldsm_x4(bh[p], sbase + OFF_B + bOff + (uint32_t)p * 16 * ROWB + koff);
#pragma unroll
            for (int mt = 0; mt < 4; ++mt)
#pragma unroll
                for (int p = 0; p < 4; ++p) {
                    mma16816(acc[mt][2 * p],     a[mt], bh[p][0], bh[p][1]);
                    mma16816(acc[mt][2 * p + 1], a[mt], bh[p][2], bh[p][3]);
                }
        }
    }

    // ---- epilogue: scale by inverse norms, ReLU, float2 stores
    const float* invd = &g_inv_dst[b * SS + n0];
#pragma unroll
    for (int mt = 0; mt < 4; ++mt) {
#pragma unroll
        for (int h = 0; h < 2; ++h) {
            int m = m0 + wm * 64 + mt * 16 + (lane >> 2) + h * 8;
            float invs = g_inv_src[b * SS + m];
            float* orow = out + ((size_t)b * SS + m) * SS + n0;
#pragma unroll
            for (int nt = 0; nt < 8; ++nt) {
                int n = wn * 64 + nt * 8 + (lane & 3) * 2;
                float2 o;
                o.x = fmaxf(acc[mt][nt][h * 2 + 0] * invs * invd[n], 0.0f);
                o.y = fmaxf(acc[mt][nt][h * 2 + 1] * invs * invd[n + 1], 0.0f);
                *(float2*)&orow[n] = o;
            }
        }
    }
}

// ---------------------------------------------------------------------------
extern "C" void kernel_launch(void* const* d_in, const int* in_sizes, int n_in,
                              void* d_out, int out_size) {
    const float* src = (const float*)d_in[0];
    const float* dst = (const float*)d_in[1];
    float* out = (float*)d_out;

    cudaFuncSetAttribute(corr_mma_kernel,
                         cudaFuncAttributeMaxDynamicSharedMemorySize, SMEM_TOTAL);

    prep_kernel<<<dim3(SS / 32, CC / 32, 2 * BB), 256>>>(src, dst);
    combine_kernel<<<2 * BB * SS / 256, 256>>>();
    corr_mma_kernel<<<dim3(SS / BN, SS / BM, BB), 256, SMEM_TOTAL>>>(out);
}

// round 7
// speedup vs baseline: 3.5919x; 1.2353x over previous
#include <cuda_runtime.h>
#include <cuda_fp16.h>
#include <cstdint>

#define BB 8
#define CC 256
#define SS 2304

#define BM 128
#define BN 128
#define BKK 32
#define KITERS (CC / BKK)   // 8
#define NSTAGE 4

// Padded SMEM row: 32 fp16 = 64B data, padded to 80B (conflict-free ldmatrix)
#define ROWB 80
#define A_TILE (BM * ROWB)               // 10240
#define B_TILE (BN * ROWB)               // 10240
#define OFF_A 0
#define OFF_B A_TILE
#define STG_BYTES (A_TILE + B_TILE)           // 20480
#define SMEM_TOTAL (NSTAGE * STG_BYTES)       // 81920 (x2 CTAs = 160KB/SM)

// ---------------- scratch (__device__ globals; no cudaMalloc allowed) ------
__device__ __half g_A[(size_t)BB * SS * CC];
__device__ __half g_B[(size_t)BB * SS * CC];
__device__ float g_part[2][8][BB * SS];   // per-32ch partial sum of squares
__device__ float g_inv_src[BB * SS];
__device__ float g_inv_dst[BB * SS];

// ---------------- PTX helpers (base ISA only) -------------------------------
__device__ __forceinline__ uint32_t smem_u32(const void* p) {
    uint32_t a;
    asm("{ .reg .u64 t; cvta.to.shared.u64 t, %1; cvt.u32.u64 %0, t; }"
        : "=r"(a) : "l"(p));
    return a;
}
__device__ __forceinline__ void cpasync16(uint32_t dst, const void* src) {
    asm volatile("cp.async.cg.shared.global [%0], [%1], 16;"
                 :: "r"(dst), "l"(src) : "memory");
}
#define CP_COMMIT() asm volatile("cp.async.commit_group;" ::: "memory")
#define CP_WAIT(n)  asm volatile("cp.async.wait_group %0;" :: "n"(n) : "memory")

__device__ __forceinline__ void ldsm_x4(uint32_t* r, uint32_t addr) {
    asm volatile("ldmatrix.sync.aligned.m8n8.x4.shared.b16 {%0,%1,%2,%3}, [%4];"
                 : "=r"(r[0]), "=r"(r[1]), "=r"(r[2]), "=r"(r[3]) : "r"(addr));
}
__device__ __forceinline__ void mma16816(float* d, const uint32_t* a,
                                         uint32_t b0, uint32_t b1) {
    asm volatile(
        "mma.sync.aligned.m16n8k16.row.col.f32.f16.f16.f32 "
        "{%0,%1,%2,%3}, {%4,%5,%6,%7}, {%8,%9}, {%0,%1,%2,%3};"
        : "+f"(d[0]), "+f"(d[1]), "+f"(d[2]), "+f"(d[3])
        : "r"(a[0]), "r"(a[1]), "r"(a[2]), "r"(a[3]), "r"(b0), "r"(b1));
}

// ---------------------------------------------------------------------------
// Kernel 1: transpose + fp16 convert + fused partial sum of squares
// ---------------------------------------------------------------------------
__global__ void prep_kernel(const float* __restrict__ src,
                            const float* __restrict__ dst) {
    __shared__ float tile[32][33];
    int z = blockIdx.z;
    int b = z >> 1, which = z & 1;
    const float* in = which ? dst : src;
    __half* outp = which ? g_B : g_A;
    int c0 = blockIdx.y * 32, s0 = blockIdx.x * 32;
    int tx = threadIdx.x & 31, ty = threadIdx.x >> 5;

    const float* p = in + (size_t)b * CC * SS;
#pragma unroll
    for (int i = 0; i < 4; ++i)
        tile[ty + i * 8][tx] = p[(size_t)(c0 + ty + i * 8) * SS + s0 + tx];
    __syncthreads();
#pragma unroll
    for (int i = 0; i < 4; ++i) {
        int srow = ty + i * 8;
        float v = tile[tx][srow];
        outp[((size_t)b * SS + s0 + srow) * CC + c0 + tx] = __float2half_rn(v);
        float sq = v * v;
#pragma unroll
        for (int off = 16; off >= 1; off >>= 1)
            sq += __shfl_xor_sync(0xffffffffu, sq, off);
        if (tx == 0)
            g_part[which][blockIdx.y][b * SS + s0 + srow] = sq;
    }
}

// ---------------------------------------------------------------------------
// Kernel 2: combine partials -> inverse norms
// ---------------------------------------------------------------------------
__global__ void combine_kernel() {
    int idx = blockIdx.x * blockDim.x + threadIdx.x;
    const int total = BB * SS;
    int which = (idx >= total) ? 1 : 0;
    int i = idx - which * total;
    float s = 0.0f;
#pragma unroll
    for (int cb = 0; cb < 8; ++cb) s += g_part[which][cb][i];
    float r = rsqrtf(s);
    if (which) g_inv_dst[i] = r; else g_inv_src[i] = r;
}

// ---------------------------------------------------------------------------
// Kernel 3: HMMA GEMM, occupancy 2. CTA 128x128, BK=32, 4-stage cp.async.
//   8 warps (4m x 2n), warp tile 32x64. fp16 x fp16 -> fp32 accumulate.
// ---------------------------------------------------------------------------
__global__ void __launch_bounds__(256, 2)
corr_mma_kernel(float* __restrict__ out) {
    extern __shared__ char smem[];
    uint32_t sb = smem_u32(smem);

    const int tid  = threadIdx.x;
    const int lane = tid & 31;
    const int wid  = tid >> 5;
    const int b  = blockIdx.z;
    const int m0 = blockIdx.y * BM;
    const int n0 = blockIdx.x * BN;

    const char* gA = (const char*)(g_A + (size_t)b * SS * CC);
    const char* gB = (const char*)(g_B + (size_t)b * SS * CC);

    // Stage loader: A 128 rows + B 128 rows, 4x16B chunks per row. 4 cp/thread.
    auto load_stage = [&](int st, int kt) {
        uint32_t sbase = sb + (uint32_t)st * STG_BYTES;
        int c0 = kt * BKK;
#pragma unroll
        for (int i = 0; i < 2; ++i) {
            int u = tid + i * 256;             // [0,512)
            int row = u >> 2, ch = u & 3;
            size_t goA = ((size_t)(m0 + row) * CC + c0) * 2 + ch * 16;
            size_t goB = ((size_t)(n0 + row) * CC + c0) * 2 + ch * 16;
            uint32_t so = (uint32_t)(row * ROWB + ch * 16);
            cpasync16(sbase + OFF_A + so, gA + goA);
            cpasync16(sbase + OFF_B + so, gB + goB);
        }
    };

    load_stage(0, 0); CP_COMMIT();
    load_stage(1, 1); CP_COMMIT();
    load_stage(2, 2); CP_COMMIT();

    float acc[2][8][4];
#pragma unroll
    for (int i = 0; i < 2; ++i)
#pragma unroll
        for (int j = 0; j < 8; ++j)
#pragma unroll
            for (int k = 0; k < 4; ++k) acc[i][j][k] = 0.0f;

    const int wm = wid & 3;    // m strip (32 rows)
    const int wn = wid >> 2;   // n strip (64 cols)

    const uint32_t aOff = (uint32_t)((wm * 32 + (lane & 15)) * ROWB + (lane >> 4) * 16);
    const uint32_t bRow = (uint32_t)(wn * 64 + (lane & 7) + ((lane >> 4) << 3));
    const uint32_t bOff = bRow * ROWB + ((lane >> 3) & 1) * 16;

    for (int kt = 0; kt < KITERS; ++kt) {
        CP_WAIT(2);
        __syncthreads();
        if (kt + 3 < KITERS) load_stage((kt + 3) % NSTAGE, kt + 3);
        CP_COMMIT();

        const uint32_t sbase = sb + (uint32_t)(kt % NSTAGE) * STG_BYTES;
#pragma unroll
        for (int ks = 0; ks < 2; ++ks) {
            const uint32_t koff = (uint32_t)ks * 32;   // k16 = 32 bytes

            uint32_t a[2][4], bh[4][4];
#pragma unroll
            for (int mt = 0; mt < 2; ++mt)
                ldsm_x4(a[mt], sbase + OFF_A + aOff + (uint32_t)mt * 16 * ROWB + koff);
#pragma unroll
            for (int p = 0; p < 4; ++p)
                ldsm_x4(bh[p], sbase + OFF_B + bOff + (uint32_t)p * 16 * ROWB + koff);
#pragma unroll
            for (int mt = 0; mt < 2; ++mt)
#pragma unroll
                for (int p = 0; p < 4; ++p) {
                    mma16816(acc[mt][2 * p],     a[mt], bh[p][0], bh[p][1]);
                    mma16816(acc[mt][2 * p + 1], a[mt], bh[p][2], bh[p][3]);
                }
        }
    }

    // ---- epilogue: scale by inverse norms, ReLU, float2 stores
    const float* invd = &g_inv_dst[b * SS + n0];
#pragma unroll
    for (int mt = 0; mt < 2; ++mt) {
#pragma unroll
        for (int h = 0; h < 2; ++h) {
            int m = m0 + wm * 32 + mt * 16 + (lane >> 2) + h * 8;
            float invs = g_inv_src[b * SS + m];
            float* orow = out + ((size_t)b * SS + m) * SS + n0;
#pragma unroll
            for (int nt = 0; nt < 8; ++nt) {
                int n = wn * 64 + nt * 8 + (lane & 3) * 2;
                float2 o;
                o.x = fmaxf(acc[mt][nt][h * 2 + 0] * invs * invd[n], 0.0f);
                o.y = fmaxf(acc[mt][nt][h * 2 + 1] * invs * invd[n + 1], 0.0f);
                *(float2*)&orow[n] = o;
            }
        }
    }
}

// ---------------------------------------------------------------------------
extern "C" void kernel_launch(void* const* d_in, const int* in_sizes, int n_in,
                              void* d_out, int out_size) {
    const float* src = (const float*)d_in[0];
    const float* dst = (const float*)d_in[1];
    float* out = (float*)d_out;

    cudaFuncSetAttribute(corr_mma_kernel,
                         cudaFuncAttributeMaxDynamicSharedMemorySize, SMEM_TOTAL);

    prep_kernel<<<dim3(SS / 32, CC / 32, 2 * BB), 256>>>(src, dst);
    combine_kernel<<<2 * BB * SS / 256, 256>>>();
    corr_mma_kernel<<<dim3(SS / BN, SS / BM, BB), 256, SMEM_TOTAL>>>(out);
}

// round 8
// speedup vs baseline: 3.6093x; 1.0048x over previous
#include <cuda_runtime.h>
#include <cuda_fp16.h>
#include <cstdint>

#define BB 8
#define CC 256
#define SS 2304

#define BM 128
#define BN 128
#define BKK 32
#define KITERS (CC / BKK)   // 8
#define NSTAGE 4

// Padded SMEM row: 32 fp16 = 64B data, padded to 80B (conflict-free ldmatrix)
#define ROWB 80
#define A_TILE (BM * ROWB)               // 10240
#define B_TILE (BN * ROWB)               // 10240
#define OFF_A 0
#define OFF_B A_TILE
#define STG_BYTES (A_TILE + B_TILE)           // 20480
#define SMEM_TOTAL (NSTAGE * STG_BYTES)       // 81920 (x2 CTAs = 160KB/SM)

// ---------------- scratch (__device__ globals; no cudaMalloc allowed) ------
__device__ __half g_A[(size_t)BB * SS * CC];
__device__ __half g_B[(size_t)BB * SS * CC];
__device__ float g_part[2][8][BB * SS];   // per-32ch partial sum of squares
__device__ float g_inv_src[BB * SS];
__device__ float g_inv_dst[BB * SS];

// ---------------- PTX helpers (base ISA only) -------------------------------
__device__ __forceinline__ uint32_t smem_u32(const void* p) {
    uint32_t a;
    asm("{ .reg .u64 t; cvta.to.shared.u64 t, %1; cvt.u32.u64 %0, t; }"
        : "=r"(a) : "l"(p));
    return a;
}
__device__ __forceinline__ void cpasync16(uint32_t dst, const void* src) {
    asm volatile("cp.async.cg.shared.global [%0], [%1], 16;"
                 :: "r"(dst), "l"(src) : "memory");
}
#define CP_COMMIT() asm volatile("cp.async.commit_group;" ::: "memory")
#define CP_WAIT(n)  asm volatile("cp.async.wait_group %0;" :: "n"(n) : "memory")

__device__ __forceinline__ void ldsm_x4(uint32_t* r, uint32_t addr) {
    asm volatile("ldmatrix.sync.aligned.m8n8.x4.shared.b16 {%0,%1,%2,%3}, [%4];"
                 : "=r"(r[0]), "=r"(r[1]), "=r"(r[2]), "=r"(r[3]) : "r"(addr));
}
__device__ __forceinline__ void mma16816(float* d, const uint32_t* a,
                                         uint32_t b0, uint32_t b1) {
    asm volatile(
        "mma.sync.aligned.m16n8k16.row.col.f32.f16.f16.f32 "
        "{%0,%1,%2,%3}, {%4,%5,%6,%7}, {%8,%9}, {%0,%1,%2,%3};"
        : "+f"(d[0]), "+f"(d[1]), "+f"(d[2]), "+f"(d[3])
        : "r"(a[0]), "r"(a[1]), "r"(a[2]), "r"(a[3]), "r"(b0), "r"(b1));
}
__device__ __forceinline__ void stg_cs_v2(float* p, float x, float y) {
    asm volatile("st.global.cs.v2.f32 [%0], {%1, %2};"
                 :: "l"(p), "f"(x), "f"(y) : "memory");
}

// ---------------------------------------------------------------------------
// Kernel 1: transpose + fp16 convert + fused partial sum of squares
//   Phase 2 mapping: thread = (s_local = tid>>3, cg = tid&7) owns 4 consecutive
//   channels of one s -> 8B vector store + 3-shfl cg-reduction.
// ---------------------------------------------------------------------------
__global__ void prep_kernel(const float* __restrict__ src,
                            const float* __restrict__ dst) {
    __shared__ float tile[32][33];
    int z = blockIdx.z;
    int b = z >> 1, which = z & 1;
    const float* in = which ? dst : src;
    __half* outp = which ? g_B : g_A;
    int c0 = blockIdx.y * 32, s0 = blockIdx.x * 32;
    int tx = threadIdx.x & 31, ty = threadIdx.x >> 5;

    const float* p = in + (size_t)b * CC * SS;
#pragma unroll
    for (int i = 0; i < 4; ++i)
        tile[ty + i * 8][tx] = p[(size_t)(c0 + ty + i * 8) * SS + s0 + tx];
    __syncthreads();

    // phase 2: 256 threads = 32 s x 8 channel-groups (4 ch each)
    const int s_local = threadIdx.x >> 3;
    const int cg = threadIdx.x & 7;
    float v0 = tile[cg * 4 + 0][s_local];
    float v1 = tile[cg * 4 + 1][s_local];
    float v2 = tile[cg * 4 + 2][s_local];
    float v3 = tile[cg * 4 + 3][s_local];

    __half2 h01 = __floats2half2_rn(v0, v1);
    __half2 h23 = __floats2half2_rn(v2, v3);
    uint2 pack = make_uint2(*(uint32_t*)&h01, *(uint32_t*)&h23);
    *(uint2*)&outp[((size_t)b * SS + s0 + s_local) * CC + c0 + cg * 4] = pack;

    float sq = v0 * v0 + v1 * v1 + v2 * v2 + v3 * v3;
    sq += __shfl_xor_sync(0xffffffffu, sq, 1);
    sq += __shfl_xor_sync(0xffffffffu, sq, 2);
    sq += __shfl_xor_sync(0xffffffffu, sq, 4);
    if (cg == 0)
        g_part[which][blockIdx.y][b * SS + s0 + s_local] = sq;
}

// ---------------------------------------------------------------------------
// Kernel 2: combine partials -> inverse norms
// ---------------------------------------------------------------------------
__global__ void combine_kernel() {
    int idx = blockIdx.x * blockDim.x + threadIdx.x;
    const int total = BB * SS;
    int which = (idx >= total) ? 1 : 0;
    int i = idx - which * total;
    float s = 0.0f;
#pragma unroll
    for (int cb = 0; cb < 8; ++cb) s += g_part[which][cb][i];
    float r = rsqrtf(s);
    if (which) g_inv_dst[i] = r; else g_inv_src[i] = r;
}

// ---------------------------------------------------------------------------
// Kernel 3: HMMA GEMM, occupancy 2. CTA 128x128, BK=32, 4-stage cp.async.
//   8 warps (4m x 2n), warp tile 32x64. fp16 x fp16 -> fp32 accumulate.
//   Epilogue uses st.global.cs (evict-first) to protect operand L2 residency.
// ---------------------------------------------------------------------------
__global__ void __launch_bounds__(256, 2)
corr_mma_kernel(float* __restrict__ out) {
    extern __shared__ char smem[];
    uint32_t sb = smem_u32(smem);

    const int tid  = threadIdx.x;
    const int lane = tid & 31;
    const int wid  = tid >> 5;
    const int b  = blockIdx.z;
    const int m0 = blockIdx.y * BM;
    const int n0 = blockIdx.x * BN;

    const char* gA = (const char*)(g_A + (size_t)b * SS * CC);
    const char* gB = (const char*)(g_B + (size_t)b * SS * CC);

    // Stage loader: A 128 rows + B 128 rows, 4x16B chunks per row. 4 cp/thread.
    auto load_stage = [&](int st, int kt) {
        uint32_t sbase = sb + (uint32_t)st * STG_BYTES;
        int c0 = kt * BKK;
#pragma unroll
        for (int i = 0; i < 2; ++i) {
            int u = tid + i * 256;             // [0,512)
            int row = u >> 2, ch = u & 3;
            size_t goA = ((size_t)(m0 + row) * CC + c0) * 2 + ch * 16;
            size_t goB = ((size_t)(n0 + row) * CC + c0) * 2 + ch * 16;
            uint32_t so = (uint32_t)(row * ROWB + ch * 16);
            cpasync16(sbase + OFF_A + so, gA + goA);
            cpasync16(sbase + OFF_B + so, gB + goB);
        }
    };

    load_stage(0, 0); CP_COMMIT();
    load_stage(1, 1); CP_COMMIT();
    load_stage(2, 2); CP_COMMIT();

    float acc[2][8][4];
#pragma unroll
    for (int i = 0; i < 2; ++i)
#pragma unroll
        for (int j = 0; j < 8; ++j)
#pragma unroll
            for (int k = 0; k < 4; ++k) acc[i][j][k] = 0.0f;

    const int wm = wid & 3;    // m strip (32 rows)
    const int wn = wid >> 2;   // n strip (64 cols)

    const uint32_t aOff = (uint32_t)((wm * 32 + (lane & 15)) * ROWB + (lane >> 4) * 16);
    const uint32_t bRow = (uint32_t)(wn * 64 + (lane & 7) + ((lane >> 4) << 3));
    const uint32_t bOff = bRow * ROWB + ((lane >> 3) & 1) * 16;

    for (int kt = 0; kt < KITERS; ++kt) {
        CP_WAIT(2);
        __syncthreads();
        if (kt + 3 < KITERS) load_stage((kt + 3) % NSTAGE, kt + 3);
        CP_COMMIT();

        const uint32_t sbase = sb + (uint32_t)(kt % NSTAGE) * STG_BYTES;
#pragma unroll
        for (int ks = 0; ks < 2; ++ks) {
            const uint32_t koff = (uint32_t)ks * 32;   // k16 = 32 bytes

            uint32_t a[2][4], bh[4][4];
#pragma unroll
            for (int mt = 0; mt < 2; ++mt)
                ldsm_x4(a[mt], sbase + OFF_A + aOff + (uint32_t)mt * 16 * ROWB + koff);
#pragma unroll
            for (int p = 0; p < 4; ++p)
                ldsm_x4(bh[p], sbase + OFF_B + bOff + (uint32_t)p * 16 * ROWB + koff);
#pragma unroll
            for (int mt = 0; mt < 2; ++mt)
#pragma unroll
                for (int p = 0; p < 4; ++p) {
                    mma16816(acc[mt][2 * p],     a[mt], bh[p][0], bh[p][1]);
                    mma16816(acc[mt][2 * p + 1], a[mt], bh[p][2], bh[p][3]);
                }
        }
    }

    // ---- epilogue: scale by inverse norms, ReLU, evict-first float2 stores
    const float* invd = &g_inv_dst[b * SS + n0];
#pragma unroll
    for (int mt = 0; mt < 2; ++mt) {
#pragma unroll
        for (int h = 0; h < 2; ++h) {
            int m = m0 + wm * 32 + mt * 16 + (lane >> 2) + h * 8;
            float invs = g_inv_src[b * SS + m];
            float* orow = out + ((size_t)b * SS + m) * SS + n0;
#pragma unroll
            for (int nt = 0; nt < 8; ++nt) {
                int n = wn * 64 + nt * 8 + (lane & 3) * 2;
                float ox = fmaxf(acc[mt][nt][h * 2 + 0] * invs * invd[n], 0.0f);
                float oy = fmaxf(acc[mt][nt][h * 2 + 1] * invs * invd[n + 1], 0.0f);
                stg_cs_v2(&orow[n], ox, oy);
            }
        }
    }
}

// ---------------------------------------------------------------------------
extern "C" void kernel_launch(void* const* d_in, const int* in_sizes, int n_in,
                              void* d_out, int out_size) {
    const float* src = (const float*)d_in[0];
    const float* dst = (const float*)d_in[1];
    float* out = (float*)d_out;

    cudaFuncSetAttribute(corr_mma_kernel,
                         cudaFuncAttributeMaxDynamicSharedMemorySize, SMEM_TOTAL);

    prep_kernel<<<dim3(SS / 32, CC / 32, 2 * BB), 256>>>(src, dst);
    combine_kernel<<<2 * BB * SS / 256, 256>>>();
    corr_mma_kernel<<<dim3(SS / BN, SS / BM, BB), 256, SMEM_TOTAL>>>(out);
}